// round 10
// baseline (speedup 1.0000x reference)
#include <cuda_runtime.h>
#include <math.h>

#define N0   4096
#define DD   320
#define DD2  640
#define KK0  3276
#define KK1  1965
#define NW   128

// ---- packed split-weight buffer offsets (float2 elements) ----
#define OFF_W0     0
#define OFF_DW0    102400
#define OFF_DW1    204800
#define OFF_WB     307200
#define OFF_CATW0  409600
#define OFF_CATW1  614400
#define OFF_AGP0   819200
#define OFF_AGP1   921600
#define OFF_UW0    1024000
#define OFF_UW1    1228800
#define OFF_WE     1433600
#define WSPLIT_TOT 1638400

__device__ float2   g_Ws  [WSPLIT_TOT];    // split weights {tf32_big, tf32_small}
__device__ float    g_part[2*N0*DD];
__device__ float    g_X0 [N0*DD];
__device__ float    g_X1d[N0*DD];
__device__ float    g_X2d[N0*DD];
__device__ float    g_Xb [N0*DD];
__device__ float    g_X1 [N0*DD];
__device__ float    g_X2 [N0*DD];
__device__ float    g_G  [N0*DD];
__device__ float    g_Xu1[N0*DD];
__device__ float    g_Xu0[N0*DD];
__device__ float    g_cat[N0*DD2];
__device__ unsigned g_bm [N0*NW];
__device__ float    g_h1 [N0];
__device__ float    g_e  [N0];
__device__ float    g_eh [N0];
__device__ float    g_sc [N0];
__device__ float    g_vals0[N0];
__device__ float    g_vals1[N0];
__device__ int      g_idx0[N0];
__device__ int      g_idx1[N0];
__device__ int      g_inv [N0];
__device__ float    g_biasGS[2*DD];

__device__ __forceinline__ unsigned tf32_rna(float x) {
    unsigned r;
    asm("cvt.rna.tf32.f32 %0, %1;" : "=r"(r) : "f"(x));
    return r;
}
__device__ __forceinline__ float2 split2(float x) {
    unsigned big = tf32_rna(x);
    float bf = __uint_as_float(big);
    unsigned sml = tf32_rna(x - bf);
    return make_float2(bf, __uint_as_float(sml));
}

__device__ __forceinline__ void mma_tf32(float* d, const unsigned* a, const unsigned* b) {
    asm volatile(
        "mma.sync.aligned.m16n8k8.row.col.f32.tf32.tf32.f32 "
        "{%0,%1,%2,%3}, {%4,%5,%6,%7}, {%8,%9}, {%0,%1,%2,%3};"
        : "+f"(d[0]), "+f"(d[1]), "+f"(d[2]), "+f"(d[3])
        : "r"(a[0]), "r"(a[1]), "r"(a[2]), "r"(a[3]), "r"(b[0]), "r"(b[1]));
}

__device__ __forceinline__ void cp_async16(unsigned daddr, const void* gptr, int src_bytes) {
    asm volatile("cp.async.cg.shared.global [%0], [%1], 16, %2;"
                 :: "r"(daddr), "l"(gptr), "r"(src_bytes));
}

// ---------------------------------------------------------------------------
// One-shot split of all weight matrices into g_Ws
// ---------------------------------------------------------------------------
__global__ void split_weights_kernel(
    const float* __restrict__ W0, const float* __restrict__ dW,
    const float* __restrict__ Wb, const float* __restrict__ agWg,
    const float* __restrict__ agWs, const float* __restrict__ agWp,
    const float* __restrict__ uW, const float* __restrict__ We,
    float2* __restrict__ out)
{
    int gid = blockIdx.x * blockDim.x + threadIdx.x;
    if (gid >= WSPLIT_TOT) return;
    int off = gid;
    float x;
    if (off < 102400)                       x = W0[off];
    else if ((off -= 102400) < 204800)      x = dW[off];
    else if ((off -= 204800) < 102400)      x = Wb[off];
    else if ((off -= 102400) < 102400)      x = agWg[off];
    else if ((off -= 102400) < 102400)      x = agWs[off];
    else if ((off -= 102400) < 102400)      x = agWg[102400 + off];
    else if ((off -= 102400) < 102400)      x = agWs[102400 + off];
    else if ((off -= 102400) < 204800)      x = agWp[off];
    else if ((off -= 204800) < 409600)      x = uW[off];
    else { off -= 409600;                   x = We[off]; }
    out[gid] = split2(x);
}

__global__ void build_mask_kernel(const float* __restrict__ A, unsigned* __restrict__ bm) {
    int gid = blockIdx.x * blockDim.x + threadIdx.x;
    float v = A[gid];
    unsigned b = __ballot_sync(0xffffffffu, v != 0.0f);
    if ((threadIdx.x & 31) == 0) bm[gid >> 5] = b;
}

// ---------------------------------------------------------------------------
// 3xTF32 tensor-core GEMM. A raw fp32 (split in registers), B pre-split.
// 4 warps in a 4x1 layout: warp w owns rows w*16..w*16+15, all 64 cols.
// gridDim.z==1 : fused epilogue, writes C directly (bias/act/res).
// gridDim.z==2 : split-K, writes raw partial P; combine_kernel finishes.
// ---------------------------------------------------------------------------
#define APITCH 36
#define BP     68
#define SMEM_GEMM (2*64*APITCH*4 + 2*32*BP*8)

__global__ __launch_bounds__(128) void gemm_tc_kernel(
    int M, int N, int kslice,
    const float* __restrict__ A, int lda,
    const float2* __restrict__ B, int ldb,
    float* __restrict__ P,
    const float* __restrict__ bias,
    float* __restrict__ C, int ldc,
    const float* __restrict__ res, int ldres,
    int act)
{
    extern __shared__ float smemf[];
    float*  As = smemf;                               // [2][64][APITCH]
    float2* Bs = (float2*)(smemf + 2 * 64 * APITCH);  // [2][32][BP]

    const int tid  = threadIdx.x;
    const int wid  = tid >> 5;
    const int lane = tid & 31;
    const int g    = lane >> 2;
    const int tg   = lane & 3;

    const int row0  = blockIdx.y * 64;
    const int col0  = blockIdx.x * 64;
    const int kbase = blockIdx.z * kslice;
    const int rb    = wid * 16;              // warp's row offset in tile

    unsigned asBase = (unsigned)__cvta_generic_to_shared(As);
    unsigned bsBase = (unsigned)__cvta_generic_to_shared(Bs);

    float acc[8][4];
#pragma unroll
    for (int nt = 0; nt < 8; nt++)
#pragma unroll
        for (int j = 0; j < 4; j++) acc[nt][j] = 0.f;

    const int nt_k = kslice / 32;

    auto issue_stage = [&](int kt, int s) {
        const int k0 = kbase + kt * 32;
#pragma unroll
        for (int i = 0; i < 4; i++) {
            int idx = i * 128 + tid;
            int r = idx >> 3, c4 = idx & 7;
            int gr = row0 + r;
            int pr = (gr < M) ? 16 : 0;
            int grc = gr < M ? gr : (M - 1);
            const float* gp = A + (size_t)grc * lda + k0 + c4 * 4;
            unsigned daddr = asBase + (unsigned)(((s * 64 + r) * APITCH + c4 * 4) * 4);
            cp_async16(daddr, gp, pr);
        }
#pragma unroll
        for (int i = 0; i < 8; i++) {
            int idx = i * 128 + tid;
            int kr = idx >> 5, c2 = (idx & 31) * 2;
            const float2* gp = B + (size_t)(k0 + kr) * ldb + col0 + c2;
            unsigned daddr = bsBase + (unsigned)(((s * 32 + kr) * BP + c2) * 8);
            cp_async16(daddr, gp, 16);
        }
        asm volatile("cp.async.commit_group;");
    };

    issue_stage(0, 0);

    for (int kt = 0; kt < nt_k; kt++) {
        asm volatile("cp.async.wait_group 0;");
        __syncthreads();
        if (kt + 1 < nt_k) issue_stage(kt + 1, (kt + 1) & 1);

        const int buf = kt & 1;
        const float*  Asb = As + buf * 64 * APITCH;
        const float2* Bb  = Bs + buf * 32 * BP;

#pragma unroll
        for (int kk = 0; kk < 4; kk++) {
            const int kc = kk * 8;
            // A fragment for this warp's 16 rows (converted ONCE per element)
            unsigned abg[4], asml[4];
            {
                float x0 = Asb[(rb + g) * APITCH + kc + tg];
                float x1 = Asb[(rb + g + 8) * APITCH + kc + tg];
                float x2 = Asb[(rb + g) * APITCH + kc + tg + 4];
                float x3 = Asb[(rb + g + 8) * APITCH + kc + tg + 4];
                abg[0] = tf32_rna(x0);
                abg[1] = tf32_rna(x1);
                abg[2] = tf32_rna(x2);
                abg[3] = tf32_rna(x3);
                asml[0] = tf32_rna(x0 - __uint_as_float(abg[0]));
                asml[1] = tf32_rna(x1 - __uint_as_float(abg[1]));
                asml[2] = tf32_rna(x2 - __uint_as_float(abg[2]));
                asml[3] = tf32_rna(x3 - __uint_as_float(abg[3]));
            }
#pragma unroll
            for (int nt = 0; nt < 8; nt++) {
                const int cb = nt * 8;
                float2 y0 = Bb[(kc + tg) * BP + cb + g];
                float2 y1 = Bb[(kc + tg + 4) * BP + cb + g];
                unsigned bbg[2], bsm[2];
                bbg[0] = __float_as_uint(y0.x);
                bsm[0] = __float_as_uint(y0.y);
                bbg[1] = __float_as_uint(y1.x);
                bsm[1] = __float_as_uint(y1.y);
                mma_tf32(acc[nt], abg, bbg);
                mma_tf32(acc[nt], abg, bsm);
                mma_tf32(acc[nt], asml, bbg);
            }
        }
        __syncthreads();
    }

    if (gridDim.z == 1) {
        // ---- fused epilogue ----
#pragma unroll
        for (int nt = 0; nt < 8; nt++) {
            const int col = col0 + nt * 8 + tg * 2;
            float b0 = bias[col], b1 = bias[col + 1];
#pragma unroll
            for (int h = 0; h < 2; h++) {
                const int r = row0 + rb + g + h * 8;
                if (r >= M) continue;
                float v0 = acc[nt][h * 2 + 0] + b0;
                float v1 = acc[nt][h * 2 + 1] + b1;
                if (act == 1) {
                    v0 = fmaxf(v0, 0.f); v1 = fmaxf(v1, 0.f);
                } else if (act == 2) {
                    v0 = 1.f / (1.f + expf(-v0));
                    v1 = 1.f / (1.f + expf(-v1));
                }
                if (res) {
                    const float2 rv = *reinterpret_cast<const float2*>(res + (size_t)r * ldres + col);
                    v0 += rv.x; v1 += rv.y;
                }
                *reinterpret_cast<float2*>(C + (size_t)r * ldc + col) = make_float2(v0, v1);
            }
        }
    } else {
        // ---- raw partial ----
        float* Pp = P + (size_t)blockIdx.z * M * N;
#pragma unroll
        for (int nt = 0; nt < 8; nt++) {
            const int col = col0 + nt * 8 + tg * 2;
#pragma unroll
            for (int h = 0; h < 2; h++) {
                const int r = row0 + rb + g + h * 8;
                if (r >= M) continue;
                float2* pp = reinterpret_cast<float2*>(Pp + (size_t)r * N + col);
                *pp = make_float2(acc[nt][h * 2 + 0], acc[nt][h * 2 + 1]);
            }
        }
    }
}

// C = act(P0 + P1 + bias) (+res after act)
__global__ void combine_kernel(int M, int N,
                               const float* __restrict__ P,
                               const float* __restrict__ bias,
                               float* __restrict__ C, int ldc,
                               const float* __restrict__ res, int ldres,
                               int act)
{
    int gid = blockIdx.x * blockDim.x + threadIdx.x;
    int total = (M * N) >> 2;
    if (gid >= total) return;
    int nq = N >> 2;
    int r = gid / nq;
    int c = (gid - r * nq) << 2;

    float4 p0 = reinterpret_cast<const float4*>(P)[gid];
    float4 p1 = reinterpret_cast<const float4*>(P + (size_t)M * N)[gid];
    float4 bv = *reinterpret_cast<const float4*>(bias + c);
    float v0 = p0.x + p1.x + bv.x;
    float v1 = p0.y + p1.y + bv.y;
    float v2 = p0.z + p1.z + bv.z;
    float v3 = p0.w + p1.w + bv.w;
    if (act == 1) {
        v0 = fmaxf(v0, 0.f); v1 = fmaxf(v1, 0.f);
        v2 = fmaxf(v2, 0.f); v3 = fmaxf(v3, 0.f);
    } else if (act == 2) {
        v0 = 1.f / (1.f + expf(-v0)); v1 = 1.f / (1.f + expf(-v1));
        v2 = 1.f / (1.f + expf(-v2)); v3 = 1.f / (1.f + expf(-v3));
    }
    if (res) {
        const float4 rv = *reinterpret_cast<const float4*>(res + (size_t)r * ldres + c);
        v0 += rv.x; v1 += rv.y; v2 += rv.z; v3 += rv.w;
    }
    *reinterpret_cast<float4*>(C + (size_t)r * ldc + c) = make_float4(v0, v1, v2, v3);
}

__global__ void gemv_e_kernel(int M, const float* __restrict__ X,
                              const float* __restrict__ w,
                              const float* __restrict__ pwb,
                              const float* __restrict__ pb,
                              const float* __restrict__ phi0,
                              float* __restrict__ h1,
                              float* __restrict__ e, float* __restrict__ eh)
{
    int warp = (blockIdx.x * blockDim.x + threadIdx.x) >> 5;
    int lane = threadIdx.x & 31;
    if (warp >= M) return;
    const float* xr = X + (size_t)warp * DD;
    float s = 0.f;
    for (int k = lane; k < DD; k += 32) s += xr[k] * w[k];
#pragma unroll
    for (int o = 16; o > 0; o >>= 1) s += __shfl_down_sync(0xffffffffu, s, o);
    if (lane == 0) {
        float h = s + pwb[0] + pb[0];
        float ex = expf(phi0[0] * h);
        h1[warp] = h;
        e[warp] = ex;
        eh[warp] = ex * h;
    }
}

__global__ void agg0_kernel(const unsigned* __restrict__ bm,
                            const float* __restrict__ e,
                            const float* __restrict__ eh,
                            float* __restrict__ scores)
{
    int r = blockIdx.x;
    int t = threadIdx.x;
    unsigned w = bm[r * NW + t];
    if ((r >> 5) == t) w |= (1u << (r & 31));
    float se = 0.f, sh = 0.f;
    while (w) {
        int b = __ffs(w) - 1;
        w &= w - 1;
        int j = t * 32 + b;
        se += e[j];
        sh += eh[j];
    }
    __shared__ float s1[128], s2[128];
    s1[t] = se; s2[t] = sh;
    __syncthreads();
    for (int o = 64; o > 0; o >>= 1) {
        if (t < o) { s1[t] += s1[t + o]; s2[t] += s2[t + o]; }
        __syncthreads();
    }
    if (t == 0) {
        float agg = (s2[0] / s1[0]) * 0.01f;
        scores[r] = 1.f / (1.f + expf(-agg));
    }
}

__global__ void agg1_kernel(const unsigned* __restrict__ bm,
                            const int* __restrict__ idx0, int n1,
                            const float* __restrict__ e,
                            const float* __restrict__ eh,
                            float* __restrict__ scores)
{
    __shared__ unsigned row[NW];
    int r = blockIdx.x;
    int t = threadIdx.x;
    int orig = idx0[r];
    if (t < NW) row[t] = bm[orig * NW + t];
    __syncthreads();
    float se = 0.f, sh = 0.f;
    for (int j = t; j < n1; j += 256) {
        int c = idx0[j];
        bool in = (row[c >> 5] >> (c & 31)) & 1u;
        if (j == r) in = true;
        if (in) { se += e[j]; sh += eh[j]; }
    }
    __shared__ float s1[256], s2[256];
    s1[t] = se; s2[t] = sh;
    __syncthreads();
    for (int o = 128; o > 0; o >>= 1) {
        if (t < o) { s1[t] += s1[t + o]; s2[t] += s2[t + o]; }
        __syncthreads();
    }
    if (t == 0) {
        float agg = (s2[0] / s1[0]) * 0.01f;
        scores[r] = 1.f / (1.f + expf(-agg));
    }
}

__global__ void rank_select_kernel(const float* __restrict__ s, int n, int kk,
                                   int* __restrict__ idx, float* __restrict__ vals)
{
    __shared__ float sh[256];
    int i = blockIdx.x * blockDim.x + threadIdx.x;
    float si = (i < n) ? s[i] : 0.f;
    int rank = 0;
    for (int base = 0; base < n; base += 256) {
        int j = base + threadIdx.x;
        sh[threadIdx.x] = (j < n) ? s[j] : -3.0e38f;
        __syncthreads();
        int lim = min(256, n - base);
        for (int t = 0; t < lim; t++) {
            float sj = sh[t];
            int j2 = base + t;
            if (sj > si || (sj == si && j2 < i)) rank++;
        }
        __syncthreads();
    }
    if (i < n && rank < kk) { idx[rank] = i; vals[rank] = si; }
}

__global__ void gather_scale_kernel(const float* __restrict__ src,
                                    const int* __restrict__ idx,
                                    const float* __restrict__ vals,
                                    int rows, float* __restrict__ dst)
{
    int gid = blockIdx.x * blockDim.x + threadIdx.x;
    if (gid >= rows * DD) return;
    int r = gid / DD, c = gid % DD;
    dst[gid] = src[(size_t)idx[r] * DD + c] * vals[r];
}

__global__ void init_inv_kernel(int* __restrict__ inv, int n) {
    int i = blockIdx.x * blockDim.x + threadIdx.x;
    if (i < n) inv[i] = -1;
}
__global__ void set_inv_kernel(int* __restrict__ inv, const int* __restrict__ idx, int kk) {
    int i = blockIdx.x * blockDim.x + threadIdx.x;
    if (i < kk) inv[idx[i]] = i;
}

// cat[r] = [ (inv[r]>=0 ? top[inv[r]] : 0) , down[r] ]   single pass
__global__ void fill_cat_kernel(float* __restrict__ cat,
                                const int* __restrict__ inv,
                                const float* __restrict__ top,
                                const float* __restrict__ down, int rows)
{
    int gid = blockIdx.x * blockDim.x + threadIdx.x;
    if (gid >= rows * DD) return;
    int r = gid / DD, c = gid % DD;
    int iv = inv[r];
    cat[(size_t)r * DD2 + c] = (iv >= 0) ? top[(size_t)iv * DD + c] : 0.f;
    cat[(size_t)r * DD2 + DD + c] = down[gid];
}

// cat[r] = [ a[r] , b[r] ]
__global__ void fill_head_kernel(float* __restrict__ cat,
                                 const float* __restrict__ a,
                                 const float* __restrict__ b, int rows)
{
    int gid = blockIdx.x * blockDim.x + threadIdx.x;
    if (gid >= rows * DD) return;
    int r = gid / DD, c = gid % DD;
    cat[(size_t)r * DD2 + c] = a[gid];
    cat[(size_t)r * DD2 + DD + c] = b[gid];
}

__global__ void add_bias_kernel(const float* __restrict__ a,
                                const float* __restrict__ b,
                                float* __restrict__ o, int n)
{
    int gid = blockIdx.x * blockDim.x + threadIdx.x;
    if (gid < n) o[gid] = a[gid] + b[gid];
}

extern "C" void kernel_launch(void* const* d_in, const int* in_sizes, int n_in,
                              void* d_out, int out_size)
{
    const float* A     = (const float*)d_in[0];
    const float* Xin   = (const float*)d_in[1];
    const float* W0    = (const float*)d_in[2];
    const float* b0    = (const float*)d_in[3];
    const float* Wb    = (const float*)d_in[4];
    const float* bb    = (const float*)d_in[5];
    const float* We    = (const float*)d_in[6];
    const float* be    = (const float*)d_in[7];
    const float* dW    = (const float*)d_in[8];
    const float* db    = (const float*)d_in[9];
    const float* uW    = (const float*)d_in[10];
    const float* ub    = (const float*)d_in[11];
    const float* pW    = (const float*)d_in[12];
    const float* pwb   = (const float*)d_in[13];
    const float* pb    = (const float*)d_in[14];
    const float* phi   = (const float*)d_in[15];
    const float* agWg  = (const float*)d_in[16];
    const float* agbg  = (const float*)d_in[17];
    const float* agWs  = (const float*)d_in[18];
    const float* agbs  = (const float*)d_in[19];
    const float* agWp  = (const float*)d_in[20];
    const float* agbp  = (const float*)d_in[21];

    float *part, *X0, *X1d, *X2d, *Xb, *X1, *X2, *G, *Xu1, *Xu0, *cat;
    float *h1, *e, *eh, *sc, *vals0, *vals1, *biasGS;
    float2* Ws;
    int *idx0, *idx1, *inv;
    unsigned* bm;
    cudaGetSymbolAddress((void**)&Ws,   g_Ws);
    cudaGetSymbolAddress((void**)&part, g_part);
    cudaGetSymbolAddress((void**)&X0,  g_X0);
    cudaGetSymbolAddress((void**)&X1d, g_X1d);
    cudaGetSymbolAddress((void**)&X2d, g_X2d);
    cudaGetSymbolAddress((void**)&Xb,  g_Xb);
    cudaGetSymbolAddress((void**)&X1,  g_X1);
    cudaGetSymbolAddress((void**)&X2,  g_X2);
    cudaGetSymbolAddress((void**)&G,   g_G);
    cudaGetSymbolAddress((void**)&Xu1, g_Xu1);
    cudaGetSymbolAddress((void**)&Xu0, g_Xu0);
    cudaGetSymbolAddress((void**)&cat, g_cat);
    cudaGetSymbolAddress((void**)&bm,  g_bm);
    cudaGetSymbolAddress((void**)&h1,  g_h1);
    cudaGetSymbolAddress((void**)&e,   g_e);
    cudaGetSymbolAddress((void**)&eh,  g_eh);
    cudaGetSymbolAddress((void**)&sc,  g_sc);
    cudaGetSymbolAddress((void**)&vals0, g_vals0);
    cudaGetSymbolAddress((void**)&vals1, g_vals1);
    cudaGetSymbolAddress((void**)&idx0, g_idx0);
    cudaGetSymbolAddress((void**)&idx1, g_idx1);
    cudaGetSymbolAddress((void**)&inv,  g_inv);
    cudaGetSymbolAddress((void**)&biasGS, g_biasGS);

    cudaFuncSetAttribute(gemm_tc_kernel,
                         cudaFuncAttributeMaxDynamicSharedMemorySize, SMEM_GEMM);

    auto gemm = [&](int M, int N, int K,
                    const float* Ap, int lda, const float2* Bp,
                    const float* bias, float* Cp, int ldc,
                    const float* res, int ldres, int act) {
        const bool split = (M < 2500);     // only KK1 starves the grid
        dim3 grid(N / 64, (M + 63) / 64, split ? 2 : 1);
        gemm_tc_kernel<<<grid, 128, SMEM_GEMM>>>(M, N, split ? K / 2 : K,
                                                 Ap, lda, Bp, DD, part,
                                                 bias, Cp, ldc, res, ldres, act);
        if (split) {
            int total = (M * N) / 4;
            combine_kernel<<<(total + 255) / 256, 256>>>(M, N, part, bias, Cp, ldc,
                                                         res, ldres, act);
        }
    };

    // ---- setup ----
    split_weights_kernel<<<(WSPLIT_TOT + 255) / 256, 256>>>(W0, dW, Wb, agWg, agWs,
                                                            agWp, uW, We, Ws);
    build_mask_kernel<<<(N0 * N0) / 256, 256>>>(A, bm);
    add_bias_kernel<<<3, 256>>>(agbg, agbs, biasGS, 2 * DD);

    // ---- encoder / down path ----
    gemm(N0, DD, DD, Xin, DD, Ws + OFF_W0, b0, X0, DD, nullptr, 0, 1);
    gemm(N0, DD, DD, X0, DD, Ws + OFF_DW0, db, X1d, DD, nullptr, 0, 1);

    gemv_e_kernel<<<(N0 + 7) / 8, 256>>>(N0, X1d, pW, pwb, pb, phi, h1, e, eh);
    agg0_kernel<<<N0, 128>>>(bm, e, eh, sc);
    rank_select_kernel<<<(N0 + 255) / 256, 256>>>(sc, N0, KK0, idx0, vals0);
    gather_scale_kernel<<<(KK0 * DD + 255) / 256, 256>>>(X1d, idx0, vals0, KK0, X1);

    gemm(KK0, DD, DD, X1, DD, Ws + OFF_DW1, db + DD, X2d, DD, nullptr, 0, 1);

    gemv_e_kernel<<<(KK0 + 7) / 8, 256>>>(KK0, X2d, pW + DD, pwb + 1, pb + 1, phi + 2, h1, e, eh);
    agg1_kernel<<<KK0, 256>>>(bm, idx0, KK0, e, eh, sc);
    rank_select_kernel<<<(KK0 + 255) / 256, 256>>>(sc, KK0, KK1, idx1, vals1);
    gather_scale_kernel<<<(KK1 * DD + 255) / 256, 256>>>(X2d, idx1, vals1, KK1, X2);

    gemm(KK1, DD, DD, X2, DD, Ws + OFF_WB, bb, Xb, DD, nullptr, 0, 1);

    // ---- up level i=0 (u=1, n=KK0) ----
    init_inv_kernel<<<(KK0 + 255) / 256, 256>>>(inv, KK0);
    set_inv_kernel<<<(KK1 + 255) / 256, 256>>>(inv, idx1, KK1);
    fill_cat_kernel<<<(KK0 * DD + 255) / 256, 256>>>(cat, inv, Xb, X2d, KK0);
    gemm(KK0, DD, DD2, cat, DD2, Ws + OFF_CATW0, biasGS, G, DD, nullptr, 0, 1);
    gemm(KK0, DD, DD,  G,   DD,  Ws + OFF_AGP0, agbp, cat + DD, DD2, nullptr, 0, 2);
    gemm(KK0, DD, DD2, cat, DD2, Ws + OFF_UW0, ub, Xu1, DD, X2d, DD, 1);

    // ---- up level i=1 (u=0, n=N0) ----
    init_inv_kernel<<<(N0 + 255) / 256, 256>>>(inv, N0);
    set_inv_kernel<<<(KK0 + 255) / 256, 256>>>(inv, idx0, KK0);
    fill_cat_kernel<<<(N0 * DD + 255) / 256, 256>>>(cat, inv, Xu1, X1d, N0);
    gemm(N0, DD, DD2, cat, DD2, Ws + OFF_CATW1, biasGS + DD, G, DD, nullptr, 0, 1);
    gemm(N0, DD, DD,  G,   DD,  Ws + OFF_AGP1, agbp + DD, cat + DD, DD2, nullptr, 0, 2);
    gemm(N0, DD, DD2, cat, DD2, Ws + OFF_UW1, ub + DD, Xu0, DD, X1d, DD, 1);

    // ---- head ----
    fill_head_kernel<<<(N0 * DD + 255) / 256, 256>>>(cat, Xu0, X0, N0);
    gemm(N0, DD, DD2, cat, DD2, Ws + OFF_WE, be, (float*)d_out, DD, nullptr, 0, 1);

    if (out_size >= 2 * N0 * DD) {
        cudaMemcpyAsync((float*)d_out + (size_t)N0 * DD, X0,
                        (size_t)N0 * DD * sizeof(float), cudaMemcpyDeviceToDevice, 0);
    }
}

// round 13
// speedup vs baseline: 1.0104x; 1.0104x over previous
#include <cuda_runtime.h>
#include <math.h>

#define N0   4096
#define DD   320
#define DD2  640
#define KK0  3276
#define KK1  1965
#define NW   128

// ---- packed split-weight buffer offsets (float2 elements) ----
#define OFF_W0     0
#define OFF_DW0    102400
#define OFF_DW1    204800
#define OFF_WB     307200
#define OFF_CATW0  409600
#define OFF_CATW1  614400
#define OFF_AGP0   819200
#define OFF_AGP1   921600
#define OFF_UW0    1024000
#define OFF_UW1    1228800
#define OFF_WE     1433600
#define WSPLIT_TOT 1638400

// scratch (static device globals; allocation-free)
__device__ float2   s_Wsplit[WSPLIT_TOT];   // split weights, cols permuted per 64-block
__device__ float    s_partial[2*N0*DD];
__device__ float    s_X0 [N0*DD];
__device__ float    s_X1d[N0*DD];
__device__ float    s_X2d[N0*DD];
__device__ float    s_Xb [N0*DD];
__device__ float    s_X1 [N0*DD];
__device__ float    s_X2 [N0*DD];
__device__ float    s_G  [N0*DD];
__device__ float    s_Xu1[N0*DD];
__device__ float    s_Xu0[N0*DD];
__device__ float    s_cat[N0*DD2];
__device__ unsigned s_bm [N0*NW];
__device__ float    s_h1 [N0];
__device__ float    s_e  [N0];
__device__ float    s_eh [N0];
__device__ float    s_sc [N0];
__device__ float    s_vals0[N0];
__device__ float    s_vals1[N0];
__device__ int      s_idx0[N0];
__device__ int      s_idx1[N0];
__device__ int      s_inv [N0];
__device__ float    s_biasGS[2*DD];

__device__ __forceinline__ unsigned cvt_tf32(float x) {
    unsigned r;
    asm("cvt.rna.tf32.f32 %0, %1;" : "=r"(r) : "f"(x));
    return r;
}
__device__ __forceinline__ float2 make_split(float x) {
    unsigned hi = cvt_tf32(x);
    float hf = __uint_as_float(hi);
    unsigned lo = cvt_tf32(x - hf);
    return make_float2(hf, __uint_as_float(lo));
}

__device__ __forceinline__ void mma8(float* d, const unsigned* a, const unsigned* b) {
    asm volatile(
        "mma.sync.aligned.m16n8k8.row.col.f32.tf32.tf32.f32 "
        "{%0,%1,%2,%3}, {%4,%5,%6,%7}, {%8,%9}, {%0,%1,%2,%3};"
        : "+f"(d[0]), "+f"(d[1]), "+f"(d[2]), "+f"(d[3])
        : "r"(a[0]), "r"(a[1]), "r"(a[2]), "r"(a[3]), "r"(b[0]), "r"(b[1]));
}

__device__ __forceinline__ void cpa16(unsigned dst, const void* src, int nbytes) {
    asm volatile("cp.async.cg.shared.global [%0], [%1], 16, %2;"
                 :: "r"(dst), "l"(src), "r"(nbytes));
}

// ---------------------------------------------------------------------------
// Split + permute all weight matrices. Permutation within each 64-col block:
// original col a*8+b -> slot b*8+a, making GEMM B-fragment reads contiguous.
// ---------------------------------------------------------------------------
__global__ void prep_weights(
    const float* __restrict__ W0, const float* __restrict__ dW,
    const float* __restrict__ Wb, const float* __restrict__ agWg,
    const float* __restrict__ agWs, const float* __restrict__ agWp,
    const float* __restrict__ uW, const float* __restrict__ We,
    float2* __restrict__ out)
{
    int gid = blockIdx.x * blockDim.x + threadIdx.x;
    if (gid >= WSPLIT_TOT) return;
    int off = gid;
    float x;
    if (off < 102400)                       x = W0[off];
    else if ((off -= 102400) < 204800)      x = dW[off];
    else if ((off -= 204800) < 102400)      x = Wb[off];
    else if ((off -= 102400) < 102400)      x = agWg[off];
    else if ((off -= 102400) < 102400)      x = agWs[off];
    else if ((off -= 102400) < 102400)      x = agWg[102400 + off];
    else if ((off -= 102400) < 102400)      x = agWs[102400 + off];
    else if ((off -= 102400) < 204800)      x = agWp[off];
    else if ((off -= 204800) < 409600)      x = uW[off];
    else { off -= 409600;                   x = We[off]; }
    int col = gid % DD;
    int pcol = (col & ~63) | ((col & 7) << 3) | ((col >> 3) & 7);
    out[gid - col + pcol] = make_split(x);
}

__global__ void mask_build(const float* __restrict__ A, unsigned* __restrict__ bm) {
    int gid = blockIdx.x * blockDim.x + threadIdx.x;
    float v = A[gid];
    unsigned b = __ballot_sync(0xffffffffu, v != 0.0f);
    if ((threadIdx.x & 31) == 0) bm[gid >> 5] = b;
}

// ---------------------------------------------------------------------------
// 3xTF32 tensor-core GEMM, split-K=2 over blockIdx.z, raw partial outputs.
// A raw fp32 (register-split once per CTA; 4x1 warp layout), B pre-split and
// column-permuted so each thread's fragments are 4x LDS.128 per row.
// ---------------------------------------------------------------------------
#define AP_   36
#define BP_   66
#define GSMEM (2*64*AP_*4 + 2*32*BP_*8)

__global__ __launch_bounds__(128) void mm3t_kernel(
    int M, int N, int kslice,
    const float* __restrict__ A, int lda,
    const float2* __restrict__ B, int ldb,
    float* __restrict__ P)
{
    extern __shared__ float dsm[];
    float*  As = dsm;                              // [2][64][AP_]
    float2* Bs = (float2*)(dsm + 2 * 64 * AP_);    // [2][32][BP_]

    const int tid  = threadIdx.x;
    const int wid  = tid >> 5;
    const int lane = tid & 31;
    const int g    = lane >> 2;
    const int tg   = lane & 3;

    const int row0  = blockIdx.y * 64;
    const int col0  = blockIdx.x * 64;
    const int kbase = blockIdx.z * kslice;
    const int rb    = wid * 16;

    unsigned aBase = (unsigned)__cvta_generic_to_shared(As);
    unsigned bBase = (unsigned)__cvta_generic_to_shared(Bs);

    float acc[8][4];
#pragma unroll
    for (int nt = 0; nt < 8; nt++) {
        acc[nt][0] = 0.f; acc[nt][1] = 0.f; acc[nt][2] = 0.f; acc[nt][3] = 0.f;
    }

    const int ktiles = kslice / 32;

    auto stage = [&](int kt, int s) {
        const int k0 = kbase + kt * 32;
#pragma unroll
        for (int i = 0; i < 4; i++) {
            int idx = i * 128 + tid;
            int r = idx >> 3, c4 = idx & 7;
            int gr = row0 + r;
            int nb = (gr < M) ? 16 : 0;
            int grc = gr < M ? gr : (M - 1);
            cpa16(aBase + (unsigned)(((s * 64 + r) * AP_ + c4 * 4) * 4),
                  A + (size_t)grc * lda + k0 + c4 * 4, nb);
        }
#pragma unroll
        for (int i = 0; i < 8; i++) {
            int idx = i * 128 + tid;
            int kr = idx >> 5, c2 = (idx & 31) * 2;
            cpa16(bBase + (unsigned)(((s * 32 + kr) * BP_ + c2) * 8),
                  B + (size_t)(k0 + kr) * ldb + col0 + c2, 16);
        }
        asm volatile("cp.async.commit_group;");
    };

    stage(0, 0);

    for (int kt = 0; kt < ktiles; kt++) {
        asm volatile("cp.async.wait_group 0;");
        __syncthreads();
        if (kt + 1 < ktiles) stage(kt + 1, (kt + 1) & 1);

        const int buf = kt & 1;
        const float*  Ab = As + buf * 64 * AP_;
        const float2* Bb = Bs + buf * 32 * BP_;

#pragma unroll
        for (int kk = 0; kk < 4; kk++) {
            const int kc = kk * 8;
            unsigned ahi[4], alo[4];
            {
                float x0 = Ab[(rb + g) * AP_ + kc + tg];
                float x1 = Ab[(rb + g + 8) * AP_ + kc + tg];
                float x2 = Ab[(rb + g) * AP_ + kc + tg + 4];
                float x3 = Ab[(rb + g + 8) * AP_ + kc + tg + 4];
                ahi[0] = cvt_tf32(x0); alo[0] = cvt_tf32(x0 - __uint_as_float(ahi[0]));
                ahi[1] = cvt_tf32(x1); alo[1] = cvt_tf32(x1 - __uint_as_float(ahi[1]));
                ahi[2] = cvt_tf32(x2); alo[2] = cvt_tf32(x2 - __uint_as_float(ahi[2]));
                ahi[3] = cvt_tf32(x3); alo[3] = cvt_tf32(x3 - __uint_as_float(ahi[3]));
            }
            const float4* rL = reinterpret_cast<const float4*>(Bb + (kc + tg) * BP_ + g * 8);
            const float4* rH = reinterpret_cast<const float4*>(Bb + (kc + tg + 4) * BP_ + g * 8);
            float4 L0 = rL[0], L1 = rL[1], L2 = rL[2], L3 = rL[3];
            float4 H0 = rH[0], H1 = rH[1], H2 = rH[2], H3 = rH[3];
            const float4 Ls[4] = {L0, L1, L2, L3};
            const float4 Hs[4] = {H0, H1, H2, H3};
#pragma unroll
            for (int nt = 0; nt < 8; nt++) {
                float4 l = Ls[nt >> 1], h = Hs[nt >> 1];
                float lx = (nt & 1) ? l.z : l.x;
                float ly = (nt & 1) ? l.w : l.y;
                float hx = (nt & 1) ? h.z : h.x;
                float hy = (nt & 1) ? h.w : h.y;
                unsigned bhi[2] = { __float_as_uint(lx), __float_as_uint(hx) };
                unsigned blo[2] = { __float_as_uint(ly), __float_as_uint(hy) };
                mma8(acc[nt], ahi, bhi);
                mma8(acc[nt], ahi, blo);
                mma8(acc[nt], alo, bhi);
            }
        }
        __syncthreads();
    }

    float* Pp = P + (size_t)blockIdx.z * M * N;
#pragma unroll
    for (int nt = 0; nt < 8; nt++) {
        const int col = col0 + nt * 8 + tg * 2;
#pragma unroll
        for (int h = 0; h < 2; h++) {
            const int r = row0 + rb + g + h * 8;
            if (r >= M) continue;
            *reinterpret_cast<float2*>(Pp + (size_t)r * N + col) =
                make_float2(acc[nt][h * 2 + 0], acc[nt][h * 2 + 1]);
        }
    }
}

// C = act(P0 + P1 + bias) (+res after act)
__global__ void finish_kernel(int M, int N,
                              const float* __restrict__ P,
                              const float* __restrict__ bias,
                              float* __restrict__ C, int ldc,
                              const float* __restrict__ res, int ldres,
                              int act)
{
    int gid = blockIdx.x * blockDim.x + threadIdx.x;
    int total = (M * N) >> 2;
    if (gid >= total) return;
    int nq = N >> 2;
    int r = gid / nq;
    int c = (gid - r * nq) << 2;

    float4 p0 = reinterpret_cast<const float4*>(P)[gid];
    float4 p1 = reinterpret_cast<const float4*>(P + (size_t)M * N)[gid];
    float4 bv = *reinterpret_cast<const float4*>(bias + c);
    float v0 = p0.x + p1.x + bv.x;
    float v1 = p0.y + p1.y + bv.y;
    float v2 = p0.z + p1.z + bv.z;
    float v3 = p0.w + p1.w + bv.w;
    if (act == 1) {
        v0 = fmaxf(v0, 0.f); v1 = fmaxf(v1, 0.f);
        v2 = fmaxf(v2, 0.f); v3 = fmaxf(v3, 0.f);
    } else if (act == 2) {
        v0 = 1.f / (1.f + expf(-v0)); v1 = 1.f / (1.f + expf(-v1));
        v2 = 1.f / (1.f + expf(-v2)); v3 = 1.f / (1.f + expf(-v3));
    }
    if (res) {
        const float4 rv = *reinterpret_cast<const float4*>(res + (size_t)r * ldres + c);
        v0 += rv.x; v1 += rv.y; v2 += rv.z; v3 += rv.w;
    }
    *reinterpret_cast<float4*>(C + (size_t)r * ldc + c) = make_float4(v0, v1, v2, v3);
}

__global__ void gemv_score(int M, const float* __restrict__ X,
                           const float* __restrict__ w,
                           const float* __restrict__ pwb,
                           const float* __restrict__ pb,
                           const float* __restrict__ phi0,
                           float* __restrict__ h1,
                           float* __restrict__ e, float* __restrict__ eh)
{
    int warp = (blockIdx.x * blockDim.x + threadIdx.x) >> 5;
    int lane = threadIdx.x & 31;
    if (warp >= M) return;
    const float* xr = X + (size_t)warp * DD;
    float s = 0.f;
    for (int k = lane; k < DD; k += 32) s += xr[k] * w[k];
#pragma unroll
    for (int o = 16; o > 0; o >>= 1) s += __shfl_down_sync(0xffffffffu, s, o);
    if (lane == 0) {
        float h = s + pwb[0] + pb[0];
        float ex = expf(phi0[0] * h);
        h1[warp] = h;
        e[warp] = ex;
        eh[warp] = ex * h;
    }
}

__global__ void agg_l0(const unsigned* __restrict__ bm,
                       const float* __restrict__ e,
                       const float* __restrict__ eh,
                       float* __restrict__ scores)
{
    int r = blockIdx.x;
    int t = threadIdx.x;
    unsigned w = bm[r * NW + t];
    if ((r >> 5) == t) w |= (1u << (r & 31));
    float se = 0.f, sh = 0.f;
    while (w) {
        int b = __ffs(w) - 1;
        w &= w - 1;
        int j = t * 32 + b;
        se += e[j];
        sh += eh[j];
    }
    __shared__ float r1[128], r2[128];
    r1[t] = se; r2[t] = sh;
    __syncthreads();
    for (int o = 64; o > 0; o >>= 1) {
        if (t < o) { r1[t] += r1[t + o]; r2[t] += r2[t + o]; }
        __syncthreads();
    }
    if (t == 0) {
        float agg = (r2[0] / r1[0]) * 0.01f;
        scores[r] = 1.f / (1.f + expf(-agg));
    }
}

__global__ void agg_l1(const unsigned* __restrict__ bm,
                       const int* __restrict__ idx0, int n1,
                       const float* __restrict__ e,
                       const float* __restrict__ eh,
                       float* __restrict__ scores)
{
    __shared__ unsigned rowbits[NW];
    int r = blockIdx.x;
    int t = threadIdx.x;
    int orig = idx0[r];
    if (t < NW) rowbits[t] = bm[orig * NW + t];
    __syncthreads();
    float se = 0.f, sh = 0.f;
    for (int j = t; j < n1; j += 256) {
        int c = idx0[j];
        bool in = (rowbits[c >> 5] >> (c & 31)) & 1u;
        if (j == r) in = true;
        if (in) { se += e[j]; sh += eh[j]; }
    }
    __shared__ float r1[256], r2[256];
    r1[t] = se; r2[t] = sh;
    __syncthreads();
    for (int o = 128; o > 0; o >>= 1) {
        if (t < o) { r1[t] += r1[t + o]; r2[t] += r2[t + o]; }
        __syncthreads();
    }
    if (t == 0) {
        float agg = (r2[0] / r1[0]) * 0.01f;
        scores[r] = 1.f / (1.f + expf(-agg));
    }
}

__global__ void topk_rank(const float* __restrict__ s, int n, int kk,
                          int* __restrict__ idx, float* __restrict__ vals)
{
    __shared__ float buf[256];
    int i = blockIdx.x * blockDim.x + threadIdx.x;
    float si = (i < n) ? s[i] : 0.f;
    int rank = 0;
    for (int base = 0; base < n; base += 256) {
        int j = base + threadIdx.x;
        buf[threadIdx.x] = (j < n) ? s[j] : -3.0e38f;
        __syncthreads();
        int lim = min(256, n - base);
        for (int t = 0; t < lim; t++) {
            float sj = buf[t];
            int j2 = base + t;
            if (sj > si || (sj == si && j2 < i)) rank++;
        }
        __syncthreads();
    }
    if (i < n && rank < kk) { idx[rank] = i; vals[rank] = si; }
}

__global__ void pool_gather(const float* __restrict__ src,
                            const int* __restrict__ idx,
                            const float* __restrict__ vals,
                            int rows, float* __restrict__ dst)
{
    int gid = blockIdx.x * blockDim.x + threadIdx.x;
    if (gid >= rows * DD) return;
    int r = gid / DD, c = gid % DD;
    dst[gid] = src[(size_t)idx[r] * DD + c] * vals[r];
}

__global__ void inv_init(int* __restrict__ inv, int n) {
    int i = blockIdx.x * blockDim.x + threadIdx.x;
    if (i < n) inv[i] = -1;
}
__global__ void inv_set(int* __restrict__ inv, const int* __restrict__ idx, int kk) {
    int i = blockIdx.x * blockDim.x + threadIdx.x;
    if (i < kk) inv[idx[i]] = i;
}

__global__ void cat_fill(float* __restrict__ cat,
                         const int* __restrict__ inv,
                         const float* __restrict__ top,
                         const float* __restrict__ down, int rows)
{
    int gid = blockIdx.x * blockDim.x + threadIdx.x;
    if (gid >= rows * DD) return;
    int r = gid / DD, c = gid % DD;
    int iv = inv[r];
    cat[(size_t)r * DD2 + c] = (iv >= 0) ? top[(size_t)iv * DD + c] : 0.f;
    cat[(size_t)r * DD2 + DD + c] = down[gid];
}

__global__ void head_fill(float* __restrict__ cat,
                          const float* __restrict__ a,
                          const float* __restrict__ b, int rows)
{
    int gid = blockIdx.x * blockDim.x + threadIdx.x;
    if (gid >= rows * DD) return;
    int r = gid / DD, c = gid % DD;
    cat[(size_t)r * DD2 + c] = a[gid];
    cat[(size_t)r * DD2 + DD + c] = b[gid];
}

__global__ void bias_sum(const float* __restrict__ a,
                         const float* __restrict__ b,
                         float* __restrict__ o, int n)
{
    int gid = blockIdx.x * blockDim.x + threadIdx.x;
    if (gid < n) o[gid] = a[gid] + b[gid];
}

extern "C" void kernel_launch(void* const* d_in, const int* in_sizes, int n_in,
                              void* d_out, int out_size)
{
    const float* A     = (const float*)d_in[0];
    const float* Xin   = (const float*)d_in[1];
    const float* W0    = (const float*)d_in[2];
    const float* b0    = (const float*)d_in[3];
    const float* Wb    = (const float*)d_in[4];
    const float* bb    = (const float*)d_in[5];
    const float* We    = (const float*)d_in[6];
    const float* be    = (const float*)d_in[7];
    const float* dW    = (const float*)d_in[8];
    const float* db    = (const float*)d_in[9];
    const float* uW    = (const float*)d_in[10];
    const float* ub    = (const float*)d_in[11];
    const float* pW    = (const float*)d_in[12];
    const float* pwb   = (const float*)d_in[13];
    const float* pb    = (const float*)d_in[14];
    const float* phi   = (const float*)d_in[15];
    const float* agWg  = (const float*)d_in[16];
    const float* agbg  = (const float*)d_in[17];
    const float* agWs  = (const float*)d_in[18];
    const float* agbs  = (const float*)d_in[19];
    const float* agWp  = (const float*)d_in[20];
    const float* agbp  = (const float*)d_in[21];

    float *part, *X0, *X1d, *X2d, *Xb, *X1, *X2, *G, *Xu1, *Xu0, *cat;
    float *h1, *e, *eh, *sc, *vals0, *vals1, *biasGS;
    float2* Ws;
    int *idx0, *idx1, *inv;
    unsigned* bm;
    cudaGetSymbolAddress((void**)&Ws,   s_Wsplit);
    cudaGetSymbolAddress((void**)&part, s_partial);
    cudaGetSymbolAddress((void**)&X0,  s_X0);
    cudaGetSymbolAddress((void**)&X1d, s_X1d);
    cudaGetSymbolAddress((void**)&X2d, s_X2d);
    cudaGetSymbolAddress((void**)&Xb,  s_Xb);
    cudaGetSymbolAddress((void**)&X1,  s_X1);
    cudaGetSymbolAddress((void**)&X2,  s_X2);
    cudaGetSymbolAddress((void**)&G,   s_G);
    cudaGetSymbolAddress((void**)&Xu1, s_Xu1);
    cudaGetSymbolAddress((void**)&Xu0, s_Xu0);
    cudaGetSymbolAddress((void**)&cat, s_cat);
    cudaGetSymbolAddress((void**)&bm,  s_bm);
    cudaGetSymbolAddress((void**)&h1,  s_h1);
    cudaGetSymbolAddress((void**)&e,   s_e);
    cudaGetSymbolAddress((void**)&eh,  s_eh);
    cudaGetSymbolAddress((void**)&sc,  s_sc);
    cudaGetSymbolAddress((void**)&vals0, s_vals0);
    cudaGetSymbolAddress((void**)&vals1, s_vals1);
    cudaGetSymbolAddress((void**)&idx0, s_idx0);
    cudaGetSymbolAddress((void**)&idx1, s_idx1);
    cudaGetSymbolAddress((void**)&inv,  s_inv);
    cudaGetSymbolAddress((void**)&biasGS, s_biasGS);

    cudaFuncSetAttribute(mm3t_kernel,
                         cudaFuncAttributeMaxDynamicSharedMemorySize, GSMEM);

    auto gemm = [&](int M, int N, int K,
                    const float* Ap, int lda, const float2* Bp,
                    const float* bias, float* Cp, int ldc,
                    const float* res, int ldres, int act) {
        dim3 grid(N / 64, (M + 63) / 64, 2);
        mm3t_kernel<<<grid, 128, GSMEM>>>(M, N, K / 2, Ap, lda, Bp, DD, part);
        int total = (M * N) / 4;
        finish_kernel<<<(total + 255) / 256, 256>>>(M, N, part, bias, Cp, ldc,
                                                    res, ldres, act);
    };

    // ---- setup ----
    prep_weights<<<(WSPLIT_TOT + 255) / 256, 256>>>(W0, dW, Wb, agWg, agWs,
                                                    agWp, uW, We, Ws);
    mask_build<<<(N0 * N0) / 256, 256>>>(A, bm);
    bias_sum<<<3, 256>>>(agbg, agbs, biasGS, 2 * DD);

    // ---- encoder / down path ----
    gemm(N0, DD, DD, Xin, DD, Ws + OFF_W0, b0, X0, DD, nullptr, 0, 1);
    gemm(N0, DD, DD, X0, DD, Ws + OFF_DW0, db, X1d, DD, nullptr, 0, 1);

    gemv_score<<<(N0 + 7) / 8, 256>>>(N0, X1d, pW, pwb, pb, phi, h1, e, eh);
    agg_l0<<<N0, 128>>>(bm, e, eh, sc);
    topk_rank<<<(N0 + 255) / 256, 256>>>(sc, N0, KK0, idx0, vals0);
    pool_gather<<<(KK0 * DD + 255) / 256, 256>>>(X1d, idx0, vals0, KK0, X1);

    gemm(KK0, DD, DD, X1, DD, Ws + OFF_DW1, db + DD, X2d, DD, nullptr, 0, 1);

    gemv_score<<<(KK0 + 7) / 8, 256>>>(KK0, X2d, pW + DD, pwb + 1, pb + 1, phi + 2, h1, e, eh);
    agg_l1<<<KK0, 256>>>(bm, idx0, KK0, e, eh, sc);
    topk_rank<<<(KK0 + 255) / 256, 256>>>(sc, KK0, KK1, idx1, vals1);
    pool_gather<<<(KK1 * DD + 255) / 256, 256>>>(X2d, idx1, vals1, KK1, X2);

    gemm(KK1, DD, DD, X2, DD, Ws + OFF_WB, bb, Xb, DD, nullptr, 0, 1);

    // ---- up level i=0 (u=1, n=KK0) ----
    inv_init<<<(KK0 + 255) / 256, 256>>>(inv, KK0);
    inv_set<<<(KK1 + 255) / 256, 256>>>(inv, idx1, KK1);
    cat_fill<<<(KK0 * DD + 255) / 256, 256>>>(cat, inv, Xb, X2d, KK0);
    gemm(KK0, DD, DD2, cat, DD2, Ws + OFF_CATW0, biasGS, G, DD, nullptr, 0, 1);
    gemm(KK0, DD, DD,  G,   DD,  Ws + OFF_AGP0, agbp, cat + DD, DD2, nullptr, 0, 2);
    gemm(KK0, DD, DD2, cat, DD2, Ws + OFF_UW0, ub, Xu1, DD, X2d, DD, 1);

    // ---- up level i=1 (u=0, n=N0) ----
    inv_init<<<(N0 + 255) / 256, 256>>>(inv, N0);
    inv_set<<<(KK0 + 255) / 256, 256>>>(inv, idx0, KK0);
    cat_fill<<<(N0 * DD + 255) / 256, 256>>>(cat, inv, Xu1, X1d, N0);
    gemm(N0, DD, DD2, cat, DD2, Ws + OFF_CATW1, biasGS + DD, G, DD, nullptr, 0, 1);
    gemm(N0, DD, DD,  G,   DD,  Ws + OFF_AGP1, agbp + DD, cat + DD, DD2, nullptr, 0, 2);
    gemm(N0, DD, DD2, cat, DD2, Ws + OFF_UW1, ub + DD, Xu0, DD, X1d, DD, 1);

    // ---- head ----
    head_fill<<<(N0 * DD + 255) / 256, 256>>>(cat, Xu0, X0, N0);
    gemm(N0, DD, DD2, cat, DD2, Ws + OFF_WE, be, (float*)d_out, DD, nullptr, 0, 1);

    if (out_size >= 2 * N0 * DD) {
        cudaMemcpyAsync((float*)d_out + (size_t)N0 * DD, X0,
                        (size_t)N0 * DD * sizeof(float), cudaMemcpyDeviceToDevice, 0);
    }
}

// round 14
// speedup vs baseline: 1.2902x; 1.2769x over previous
#include <cuda_runtime.h>
#include <cuda_bf16.h>
#include <math.h>

#define N0   4096
#define DD   320
#define DD2  640
#define KK0  3276
#define KK1  1965
#define NW   128

// ---- tf32 split-weight buffer (down-path only), float2 units ----
#define OFF_W0     0
#define OFF_DW0    102400
#define OFF_DW1    204800
#define TF32_TOT   307200

// ---- bf16 fragment buffer (up-path), uint32 units ----
#define FB_WB      0
#define FB_CATW0   102400
#define FB_CATW1   307200
#define FB_AGP0    512000
#define FB_AGP1    614400
#define FB_UW0     716800
#define FB_UW1     921600
#define FB_WE      1126400
#define FRAG_TOT   1331200
#define FRAG_SITES 665600

__device__ float2   s_Wsplit[TF32_TOT];
__device__ unsigned s_Wfrag [FRAG_TOT];
__device__ float    s_partial[2*N0*DD];
__device__ float    s_X0 [N0*DD];
__device__ float    s_X1d[N0*DD];
__device__ float    s_X2d[N0*DD];
__device__ float    s_Xb [N0*DD];
__device__ float    s_X1 [N0*DD];
__device__ float    s_X2 [N0*DD];
__device__ float    s_G  [N0*DD];
__device__ float    s_Xu1[N0*DD];
__device__ float    s_Xu0[N0*DD];
__device__ float    s_cat[N0*DD2];
__device__ unsigned s_bm [N0*NW];
__device__ float    s_h1 [N0];
__device__ float    s_e  [N0];
__device__ float    s_eh [N0];
__device__ float    s_sc [N0];
__device__ float    s_vals0[N0];
__device__ float    s_vals1[N0];
__device__ int      s_idx0[N0];
__device__ int      s_idx1[N0];
__device__ int      s_inv [N0];
__device__ float    s_biasGS[2*DD];

__device__ __forceinline__ unsigned cvt_tf32(float x) {
    unsigned r;
    asm("cvt.rna.tf32.f32 %0, %1;" : "=r"(r) : "f"(x));
    return r;
}
__device__ __forceinline__ float2 make_split(float x) {
    unsigned hi = cvt_tf32(x);
    float hf = __uint_as_float(hi);
    unsigned lo = cvt_tf32(x - hf);
    return make_float2(hf, __uint_as_float(lo));
}

__device__ __forceinline__ void mma8(float* d, const unsigned* a, const unsigned* b) {
    asm volatile(
        "mma.sync.aligned.m16n8k8.row.col.f32.tf32.tf32.f32 "
        "{%0,%1,%2,%3}, {%4,%5,%6,%7}, {%8,%9}, {%0,%1,%2,%3};"
        : "+f"(d[0]), "+f"(d[1]), "+f"(d[2]), "+f"(d[3])
        : "r"(a[0]), "r"(a[1]), "r"(a[2]), "r"(a[3]), "r"(b[0]), "r"(b[1]));
}

__device__ __forceinline__ void mma16(float* d, const unsigned* a, unsigned b0, unsigned b1) {
    asm volatile(
        "mma.sync.aligned.m16n8k16.row.col.f32.bf16.bf16.f32 "
        "{%0,%1,%2,%3}, {%4,%5,%6,%7}, {%8,%9}, {%0,%1,%2,%3};"
        : "+f"(d[0]), "+f"(d[1]), "+f"(d[2]), "+f"(d[3])
        : "r"(a[0]), "r"(a[1]), "r"(a[2]), "r"(a[3]), "r"(b0), "r"(b1));
}

__device__ __forceinline__ void cpa16(unsigned dst, const void* src, int nbytes) {
    asm volatile("cp.async.cg.shared.global [%0], [%1], 16, %2;"
                 :: "r"(dst), "l"(src), "r"(nbytes));
}

// bf16 split of a float2 -> packed hi (returned) and packed lo
__device__ __forceinline__ unsigned split_bf2(float2 v, unsigned* lo) {
    __nv_bfloat162 h = __floats2bfloat162_rn(v.x, v.y);
    float2 hf = __bfloat1622float2(h);
    __nv_bfloat162 l = __floats2bfloat162_rn(v.x - hf.x, v.y - hf.y);
    *lo = *reinterpret_cast<unsigned*>(&l);
    return *reinterpret_cast<unsigned*>(&h);
}

// ---------------------------------------------------------------------------
// tf32 split + 64-col permutation (down-path weights: W0, dW0, dW1)
// ---------------------------------------------------------------------------
__global__ void prep_tf32(const float* __restrict__ W0,
                          const float* __restrict__ dW,
                          float2* __restrict__ out)
{
    int gid = blockIdx.x * blockDim.x + threadIdx.x;
    if (gid >= TF32_TOT) return;
    float x = (gid < 102400) ? W0[gid] : dW[gid - 102400];
    int col = gid % DD;
    int pcol = (col & ~63) | ((col & 7) << 3) | ((col >> 3) & 7);
    out[gid - col + pcol] = make_split(x);
}

// ---------------------------------------------------------------------------
// bf16 split + fragment-major packing (up-path weights).
// Block = (kb 16 rows) x (cbi 64 cols) = 1024 uint32 (hi [0,512), lo [512,1024)).
// Within: q = nt*2+reg; idx = (q>>2)*128 + lane*4 + (q&3), lane = g*4+tg.
// reg0 pair = k rows (tg*2, tg*2+1); reg1 = (tg*2+8, tg*2+9); col = cbi*64+nt*8+g.
// ---------------------------------------------------------------------------
__global__ void prep_frag(const float* __restrict__ Wb,
                          const float* __restrict__ agWg,
                          const float* __restrict__ agWs,
                          const float* __restrict__ agWp,
                          const float* __restrict__ uW,
                          const float* __restrict__ We,
                          unsigned* __restrict__ out)
{
    int gid = blockIdx.x * blockDim.x + threadIdx.x;
    if (gid >= FRAG_SITES) return;
    int s = gid;
    const float* src = nullptr;
    long fb = 0;
    int catL = -1;
    if (s < 51200)                    { src = Wb;             fb = FB_WB;    }
    else if ((s -= 51200) < 102400)   { catL = 0;             fb = FB_CATW0; }
    else if ((s -= 102400) < 102400)  { catL = 1;             fb = FB_CATW1; }
    else if ((s -= 102400) < 51200)   { src = agWp;           fb = FB_AGP0;  }
    else if ((s -= 51200) < 51200)    { src = agWp + 102400;  fb = FB_AGP1;  }
    else if ((s -= 51200) < 102400)   { src = uW;             fb = FB_UW0;   }
    else if ((s -= 102400) < 102400)  { src = uW + 204800;    fb = FB_UW1;   }
    else { s -= 102400;                 src = We;             fb = FB_WE;    }

    int block = s >> 9;
    int r = s & 511;
    int tg = r >> 7, g = (r >> 4) & 7, nt = (r >> 1) & 7, reg = r & 1;
    int kb = block / 5, cbi = block % 5;
    int k0 = kb * 16 + tg * 2 + reg * 8;
    int col = cbi * 64 + nt * 8 + g;
    float x0, x1;
    if (catL >= 0) {
        const float* g0 = agWg + catL * 102400;
        const float* s0 = agWs + catL * 102400;
        x0 = (k0 < 320) ? g0[k0 * 320 + col] : s0[(k0 - 320) * 320 + col];
        x1 = (k0 + 1 < 320) ? g0[(k0 + 1) * 320 + col] : s0[(k0 + 1 - 320) * 320 + col];
    } else {
        x0 = src[(size_t)k0 * 320 + col];
        x1 = src[(size_t)(k0 + 1) * 320 + col];
    }
    __nv_bfloat162 h = __floats2bfloat162_rn(x0, x1);
    float2 hf = __bfloat1622float2(h);
    __nv_bfloat162 l = __floats2bfloat162_rn(x0 - hf.x, x1 - hf.y);
    int q = nt * 2 + reg;
    int idx = (q >> 2) * 128 + (g * 4 + tg) * 4 + (q & 3);
    unsigned* blk = out + fb + (size_t)block * 1024;
    blk[idx]       = *reinterpret_cast<unsigned*>(&h);
    blk[512 + idx] = *reinterpret_cast<unsigned*>(&l);
}

__global__ void mask_build(const float* __restrict__ A, unsigned* __restrict__ bm) {
    int gid = blockIdx.x * blockDim.x + threadIdx.x;
    float v = A[gid];
    unsigned b = __ballot_sync(0xffffffffu, v != 0.0f);
    if ((threadIdx.x & 31) == 0) bm[gid >> 5] = b;
}

// ---------------------------------------------------------------------------
// tf32x3 GEMM (down path; unchanged from R13)
// ---------------------------------------------------------------------------
#define AP_   36
#define BP_   66
#define GSMEM (2*64*AP_*4 + 2*32*BP_*8)

__global__ __launch_bounds__(128) void mm3t_kernel(
    int M, int N, int kslice,
    const float* __restrict__ A, int lda,
    const float2* __restrict__ B, int ldb,
    float* __restrict__ P)
{
    extern __shared__ float dsm[];
    float*  As = dsm;
    float2* Bs = (float2*)(dsm + 2 * 64 * AP_);

    const int tid  = threadIdx.x;
    const int wid  = tid >> 5;
    const int lane = tid & 31;
    const int g    = lane >> 2;
    const int tg   = lane & 3;

    const int row0  = blockIdx.y * 64;
    const int col0  = blockIdx.x * 64;
    const int kbase = blockIdx.z * kslice;
    const int rb    = wid * 16;

    unsigned aBase = (unsigned)__cvta_generic_to_shared(As);
    unsigned bBase = (unsigned)__cvta_generic_to_shared(Bs);

    float acc[8][4];
#pragma unroll
    for (int nt = 0; nt < 8; nt++) {
        acc[nt][0] = 0.f; acc[nt][1] = 0.f; acc[nt][2] = 0.f; acc[nt][3] = 0.f;
    }

    const int ktiles = kslice / 32;

    auto stage = [&](int kt, int s) {
        const int k0 = kbase + kt * 32;
#pragma unroll
        for (int i = 0; i < 4; i++) {
            int idx = i * 128 + tid;
            int r = idx >> 3, c4 = idx & 7;
            int gr = row0 + r;
            int nb = (gr < M) ? 16 : 0;
            int grc = gr < M ? gr : (M - 1);
            cpa16(aBase + (unsigned)(((s * 64 + r) * AP_ + c4 * 4) * 4),
                  A + (size_t)grc * lda + k0 + c4 * 4, nb);
        }
#pragma unroll
        for (int i = 0; i < 8; i++) {
            int idx = i * 128 + tid;
            int kr = idx >> 5, c2 = (idx & 31) * 2;
            cpa16(bBase + (unsigned)(((s * 32 + kr) * BP_ + c2) * 8),
                  B + (size_t)(k0 + kr) * ldb + col0 + c2, 16);
        }
        asm volatile("cp.async.commit_group;");
    };

    stage(0, 0);

    for (int kt = 0; kt < ktiles; kt++) {
        asm volatile("cp.async.wait_group 0;");
        __syncthreads();
        if (kt + 1 < ktiles) stage(kt + 1, (kt + 1) & 1);

        const int buf = kt & 1;
        const float*  Ab = As + buf * 64 * AP_;
        const float2* Bb = Bs + buf * 32 * BP_;

#pragma unroll
        for (int kk = 0; kk < 4; kk++) {
            const int kc = kk * 8;
            unsigned ahi[4], alo[4];
            {
                float x0 = Ab[(rb + g) * AP_ + kc + tg];
                float x1 = Ab[(rb + g + 8) * AP_ + kc + tg];
                float x2 = Ab[(rb + g) * AP_ + kc + tg + 4];
                float x3 = Ab[(rb + g + 8) * AP_ + kc + tg + 4];
                ahi[0] = cvt_tf32(x0); alo[0] = cvt_tf32(x0 - __uint_as_float(ahi[0]));
                ahi[1] = cvt_tf32(x1); alo[1] = cvt_tf32(x1 - __uint_as_float(ahi[1]));
                ahi[2] = cvt_tf32(x2); alo[2] = cvt_tf32(x2 - __uint_as_float(ahi[2]));
                ahi[3] = cvt_tf32(x3); alo[3] = cvt_tf32(x3 - __uint_as_float(ahi[3]));
            }
            const float4* rL = reinterpret_cast<const float4*>(Bb + (kc + tg) * BP_ + g * 8);
            const float4* rH = reinterpret_cast<const float4*>(Bb + (kc + tg + 4) * BP_ + g * 8);
            float4 Ls[4] = {rL[0], rL[1], rL[2], rL[3]};
            float4 Hs[4] = {rH[0], rH[1], rH[2], rH[3]};
#pragma unroll
            for (int nt = 0; nt < 8; nt++) {
                float4 l = Ls[nt >> 1], h = Hs[nt >> 1];
                float lx = (nt & 1) ? l.z : l.x;
                float ly = (nt & 1) ? l.w : l.y;
                float hx = (nt & 1) ? h.z : h.x;
                float hy = (nt & 1) ? h.w : h.y;
                unsigned bhi[2] = { __float_as_uint(lx), __float_as_uint(hx) };
                unsigned blo[2] = { __float_as_uint(ly), __float_as_uint(hy) };
                mma8(acc[nt], ahi, bhi);
                mma8(acc[nt], ahi, blo);
                mma8(acc[nt], alo, bhi);
            }
        }
        __syncthreads();
    }

    float* Pp = P + (size_t)blockIdx.z * M * N;
#pragma unroll
    for (int nt = 0; nt < 8; nt++) {
        const int col = col0 + nt * 8 + tg * 2;
#pragma unroll
        for (int h = 0; h < 2; h++) {
            const int r = row0 + rb + g + h * 8;
            if (r >= M) continue;
            *reinterpret_cast<float2*>(Pp + (size_t)r * N + col) =
                make_float2(acc[nt][h * 2 + 0], acc[nt][h * 2 + 1]);
        }
    }
}

// ---------------------------------------------------------------------------
// bf16x3 GEMM (up path). B pre-packed in fragment-major layout.
// ---------------------------------------------------------------------------
#define GS_BF (2*64*AP_*4 + 2*2048*4)

__global__ __launch_bounds__(128) void mmbf_kernel(
    int M, int N, int kslice,
    const float* __restrict__ A, int lda,
    const unsigned* __restrict__ Bf,
    float* __restrict__ P)
{
    extern __shared__ float dsm[];
    float*    As = dsm;                              // [2][64][AP_]
    unsigned* Bs = (unsigned*)(dsm + 2 * 64 * AP_);  // [2][2048]

    const int tid  = threadIdx.x;
    const int wid  = tid >> 5;
    const int lane = tid & 31;
    const int g    = lane >> 2;
    const int tg   = lane & 3;

    const int row0  = blockIdx.y * 64;
    const int col0  = blockIdx.x * 64;
    const int kbase = blockIdx.z * kslice;
    const int rb    = wid * 16;

    unsigned aBase = (unsigned)__cvta_generic_to_shared(As);
    unsigned bBase = (unsigned)__cvta_generic_to_shared(Bs);

    float acc[8][4];
#pragma unroll
    for (int nt = 0; nt < 8; nt++) {
        acc[nt][0] = 0.f; acc[nt][1] = 0.f; acc[nt][2] = 0.f; acc[nt][3] = 0.f;
    }

    const int ktiles = kslice / 32;

    auto stage = [&](int kt, int s) {
        const int k0 = kbase + kt * 32;
#pragma unroll
        for (int i = 0; i < 4; i++) {
            int idx = i * 128 + tid;
            int r = idx >> 3, c4 = idx & 7;
            int gr = row0 + r;
            int nb = (gr < M) ? 16 : 0;
            int grc = gr < M ? gr : (M - 1);
            cpa16(aBase + (unsigned)(((s * 64 + r) * AP_ + c4 * 4) * 4),
                  A + (size_t)grc * lda + k0 + c4 * 4, nb);
        }
        const int kb0 = k0 >> 4;
#pragma unroll
        for (int i = 0; i < 4; i++) {
            int c = i * 128 + tid;            // 512 chunks of 16B
            int sub = c >> 8, i16 = c & 255;
            const unsigned* src = Bf + ((size_t)(kb0 + sub) * 5 + blockIdx.x) * 1024 + i16 * 4;
            cpa16(bBase + (unsigned)((s * 2048 + sub * 1024 + i16 * 4) * 4), src, 16);
        }
        asm volatile("cp.async.commit_group;");
    };

    stage(0, 0);

    for (int kt = 0; kt < ktiles; kt++) {
        asm volatile("cp.async.wait_group 0;");
        __syncthreads();
        if (kt + 1 < ktiles) stage(kt + 1, (kt + 1) & 1);

        const int buf = kt & 1;
        const float* Ab = As + buf * 64 * AP_;

#pragma unroll
        for (int sub = 0; sub < 2; sub++) {
            const unsigned* Bb = Bs + buf * 2048 + sub * 1024;
            // A fragments: rows rb+g / rb+g+8, k pairs tg*2 and tg*2+8 (within sub*16)
            float2 p0 = *reinterpret_cast<const float2*>(&Ab[(rb + g) * AP_ + sub * 16 + tg * 2]);
            float2 p1 = *reinterpret_cast<const float2*>(&Ab[(rb + g + 8) * AP_ + sub * 16 + tg * 2]);
            float2 p2 = *reinterpret_cast<const float2*>(&Ab[(rb + g) * AP_ + sub * 16 + tg * 2 + 8]);
            float2 p3 = *reinterpret_cast<const float2*>(&Ab[(rb + g + 8) * AP_ + sub * 16 + tg * 2 + 8]);
            unsigned ahi[4], alo[4];
            ahi[0] = split_bf2(p0, &alo[0]);
            ahi[1] = split_bf2(p1, &alo[1]);
            ahi[2] = split_bf2(p2, &alo[2]);
            ahi[3] = split_bf2(p3, &alo[3]);
            // B fragments: chunk-interleaved, conflict-free LDS.128
            const uint4* bh4 = reinterpret_cast<const uint4*>(Bb + lane * 4);
            const uint4* bl4 = reinterpret_cast<const uint4*>(Bb + 512 + lane * 4);
            uint4 bh[4], bl[4];
#pragma unroll
            for (int j = 0; j < 4; j++) { bh[j] = bh4[j * 32]; bl[j] = bl4[j * 32]; }
#pragma unroll
            for (int nt = 0; nt < 8; nt++) {
                uint4 h = bh[nt >> 1], l = bl[nt >> 1];
                unsigned h0 = (nt & 1) ? h.z : h.x;
                unsigned h1 = (nt & 1) ? h.w : h.y;
                unsigned l0 = (nt & 1) ? l.z : l.x;
                unsigned l1 = (nt & 1) ? l.w : l.y;
                mma16(acc[nt], ahi, h0, h1);
                mma16(acc[nt], ahi, l0, l1);
                mma16(acc[nt], alo, h0, h1);
            }
        }
        __syncthreads();
    }

    float* Pp = P + (size_t)blockIdx.z * M * N;
#pragma unroll
    for (int nt = 0; nt < 8; nt++) {
        const int col = col0 + nt * 8 + tg * 2;
#pragma unroll
        for (int h = 0; h < 2; h++) {
            const int r = row0 + rb + g + h * 8;
            if (r >= M) continue;
            *reinterpret_cast<float2*>(Pp + (size_t)r * N + col) =
                make_float2(acc[nt][h * 2 + 0], acc[nt][h * 2 + 1]);
        }
    }
}

// C = act(P0 + P1 + bias) (+res after act)
__global__ void finish_kernel(int M, int N,
                              const float* __restrict__ P,
                              const float* __restrict__ bias,
                              float* __restrict__ C, int ldc,
                              const float* __restrict__ res, int ldres,
                              int act)
{
    int gid = blockIdx.x * blockDim.x + threadIdx.x;
    int total = (M * N) >> 2;
    if (gid >= total) return;
    int nq = N >> 2;
    int r = gid / nq;
    int c = (gid - r * nq) << 2;

    float4 p0 = reinterpret_cast<const float4*>(P)[gid];
    float4 p1 = reinterpret_cast<const float4*>(P + (size_t)M * N)[gid];
    float4 bv = *reinterpret_cast<const float4*>(bias + c);
    float v0 = p0.x + p1.x + bv.x;
    float v1 = p0.y + p1.y + bv.y;
    float v2 = p0.z + p1.z + bv.z;
    float v3 = p0.w + p1.w + bv.w;
    if (act == 1) {
        v0 = fmaxf(v0, 0.f); v1 = fmaxf(v1, 0.f);
        v2 = fmaxf(v2, 0.f); v3 = fmaxf(v3, 0.f);
    } else if (act == 2) {
        v0 = 1.f / (1.f + expf(-v0)); v1 = 1.f / (1.f + expf(-v1));
        v2 = 1.f / (1.f + expf(-v2)); v3 = 1.f / (1.f + expf(-v3));
    }
    if (res) {
        const float4 rv = *reinterpret_cast<const float4*>(res + (size_t)r * ldres + c);
        v0 += rv.x; v1 += rv.y; v2 += rv.z; v3 += rv.w;
    }
    *reinterpret_cast<float4*>(C + (size_t)r * ldc + c) = make_float4(v0, v1, v2, v3);
}

__global__ void gemv_score(int M, const float* __restrict__ X,
                           const float* __restrict__ w,
                           const float* __restrict__ pwb,
                           const float* __restrict__ pb,
                           const float* __restrict__ phi0,
                           float* __restrict__ h1,
                           float* __restrict__ e, float* __restrict__ eh)
{
    int warp = (blockIdx.x * blockDim.x + threadIdx.x) >> 5;
    int lane = threadIdx.x & 31;
    if (warp >= M) return;
    const float* xr = X + (size_t)warp * DD;
    float s = 0.f;
    for (int k = lane; k < DD; k += 32) s += xr[k] * w[k];
#pragma unroll
    for (int o = 16; o > 0; o >>= 1) s += __shfl_down_sync(0xffffffffu, s, o);
    if (lane == 0) {
        float h = s + pwb[0] + pb[0];
        float ex = expf(phi0[0] * h);
        h1[warp] = h;
        e[warp] = ex;
        eh[warp] = ex * h;
    }
}

__global__ void agg_l0(const unsigned* __restrict__ bm,
                       const float* __restrict__ e,
                       const float* __restrict__ eh,
                       float* __restrict__ scores)
{
    int r = blockIdx.x;
    int t = threadIdx.x;
    unsigned w = bm[r * NW + t];
    if ((r >> 5) == t) w |= (1u << (r & 31));
    float se = 0.f, sh = 0.f;
    while (w) {
        int b = __ffs(w) - 1;
        w &= w - 1;
        int j = t * 32 + b;
        se += e[j];
        sh += eh[j];
    }
    __shared__ float r1[128], r2[128];
    r1[t] = se; r2[t] = sh;
    __syncthreads();
    for (int o = 64; o > 0; o >>= 1) {
        if (t < o) { r1[t] += r1[t + o]; r2[t] += r2[t + o]; }
        __syncthreads();
    }
    if (t == 0) {
        float agg = (r2[0] / r1[0]) * 0.01f;
        scores[r] = 1.f / (1.f + expf(-agg));
    }
}

__global__ void agg_l1(const unsigned* __restrict__ bm,
                       const int* __restrict__ idx0, int n1,
                       const float* __restrict__ e,
                       const float* __restrict__ eh,
                       float* __restrict__ scores)
{
    __shared__ unsigned rowbits[NW];
    int r = blockIdx.x;
    int t = threadIdx.x;
    int orig = idx0[r];
    if (t < NW) rowbits[t] = bm[orig * NW + t];
    __syncthreads();
    float se = 0.f, sh = 0.f;
    for (int j = t; j < n1; j += 256) {
        int c = idx0[j];
        bool in = (rowbits[c >> 5] >> (c & 31)) & 1u;
        if (j == r) in = true;
        if (in) { se += e[j]; sh += eh[j]; }
    }
    __shared__ float r1[256], r2[256];
    r1[t] = se; r2[t] = sh;
    __syncthreads();
    for (int o = 128; o > 0; o >>= 1) {
        if (t < o) { r1[t] += r1[t + o]; r2[t] += r2[t + o]; }
        __syncthreads();
    }
    if (t == 0) {
        float agg = (r2[0] / r1[0]) * 0.01f;
        scores[r] = 1.f / (1.f + expf(-agg));
    }
}

__global__ void topk_rank(const float* __restrict__ s, int n, int kk,
                          int* __restrict__ idx, float* __restrict__ vals)
{
    __shared__ float buf[256];
    int i = blockIdx.x * blockDim.x + threadIdx.x;
    float si = (i < n) ? s[i] : 0.f;
    int rank = 0;
    for (int base = 0; base < n; base += 256) {
        int j = base + threadIdx.x;
        buf[threadIdx.x] = (j < n) ? s[j] : -3.0e38f;
        __syncthreads();
        int lim = min(256, n - base);
        for (int t = 0; t < lim; t++) {
            float sj = buf[t];
            int j2 = base + t;
            if (sj > si || (sj == si && j2 < i)) rank++;
        }
        __syncthreads();
    }
    if (i < n && rank < kk) { idx[rank] = i; vals[rank] = si; }
}

__global__ void pool_gather(const float* __restrict__ src,
                            const int* __restrict__ idx,
                            const float* __restrict__ vals,
                            int rows, float* __restrict__ dst)
{
    int gid = blockIdx.x * blockDim.x + threadIdx.x;
    if (gid >= rows * DD) return;
    int r = gid / DD, c = gid % DD;
    dst[gid] = src[(size_t)idx[r] * DD + c] * vals[r];
}

__global__ void inv_init(int* __restrict__ inv, int n) {
    int i = blockIdx.x * blockDim.x + threadIdx.x;
    if (i < n) inv[i] = -1;
}
__global__ void inv_set(int* __restrict__ inv, const int* __restrict__ idx, int kk) {
    int i = blockIdx.x * blockDim.x + threadIdx.x;
    if (i < kk) inv[idx[i]] = i;
}

__global__ void cat_fill(float* __restrict__ cat,
                         const int* __restrict__ inv,
                         const float* __restrict__ top,
                         const float* __restrict__ down, int rows)
{
    int gid = blockIdx.x * blockDim.x + threadIdx.x;
    if (gid >= rows * DD) return;
    int r = gid / DD, c = gid % DD;
    int iv = inv[r];
    cat[(size_t)r * DD2 + c] = (iv >= 0) ? top[(size_t)iv * DD + c] : 0.f;
    cat[(size_t)r * DD2 + DD + c] = down[gid];
}

__global__ void head_fill(float* __restrict__ cat,
                          const float* __restrict__ a,
                          const float* __restrict__ b, int rows)
{
    int gid = blockIdx.x * blockDim.x + threadIdx.x;
    if (gid >= rows * DD) return;
    int r = gid / DD, c = gid % DD;
    cat[(size_t)r * DD2 + c] = a[gid];
    cat[(size_t)r * DD2 + DD + c] = b[gid];
}

__global__ void bias_sum(const float* __restrict__ a,
                         const float* __restrict__ b,
                         float* __restrict__ o, int n)
{
    int gid = blockIdx.x * blockDim.x + threadIdx.x;
    if (gid < n) o[gid] = a[gid] + b[gid];
}

extern "C" void kernel_launch(void* const* d_in, const int* in_sizes, int n_in,
                              void* d_out, int out_size)
{
    const float* A     = (const float*)d_in[0];
    const float* Xin   = (const float*)d_in[1];
    const float* W0    = (const float*)d_in[2];
    const float* b0    = (const float*)d_in[3];
    const float* Wb    = (const float*)d_in[4];
    const float* bb    = (const float*)d_in[5];
    const float* We    = (const float*)d_in[6];
    const float* be    = (const float*)d_in[7];
    const float* dW    = (const float*)d_in[8];
    const float* db    = (const float*)d_in[9];
    const float* uW    = (const float*)d_in[10];
    const float* ub    = (const float*)d_in[11];
    const float* pW    = (const float*)d_in[12];
    const float* pwb   = (const float*)d_in[13];
    const float* pb    = (const float*)d_in[14];
    const float* phi   = (const float*)d_in[15];
    const float* agWg  = (const float*)d_in[16];
    const float* agbg  = (const float*)d_in[17];
    const float* agWs  = (const float*)d_in[18];
    const float* agbs  = (const float*)d_in[19];
    const float* agWp  = (const float*)d_in[20];
    const float* agbp  = (const float*)d_in[21];

    float *part, *X0, *X1d, *X2d, *Xb, *X1, *X2, *G, *Xu1, *Xu0, *cat;
    float *h1, *e, *eh, *sc, *vals0, *vals1, *biasGS;
    float2* Ws;
    unsigned *Fr, *bm;
    int *idx0, *idx1, *inv;
    cudaGetSymbolAddress((void**)&Ws,   s_Wsplit);
    cudaGetSymbolAddress((void**)&Fr,   s_Wfrag);
    cudaGetSymbolAddress((void**)&part, s_partial);
    cudaGetSymbolAddress((void**)&X0,  s_X0);
    cudaGetSymbolAddress((void**)&X1d, s_X1d);
    cudaGetSymbolAddress((void**)&X2d, s_X2d);
    cudaGetSymbolAddress((void**)&Xb,  s_Xb);
    cudaGetSymbolAddress((void**)&X1,  s_X1);
    cudaGetSymbolAddress((void**)&X2,  s_X2);
    cudaGetSymbolAddress((void**)&G,   s_G);
    cudaGetSymbolAddress((void**)&Xu1, s_Xu1);
    cudaGetSymbolAddress((void**)&Xu0, s_Xu0);
    cudaGetSymbolAddress((void**)&cat, s_cat);
    cudaGetSymbolAddress((void**)&bm,  s_bm);
    cudaGetSymbolAddress((void**)&h1,  s_h1);
    cudaGetSymbolAddress((void**)&e,   s_e);
    cudaGetSymbolAddress((void**)&eh,  s_eh);
    cudaGetSymbolAddress((void**)&sc,  s_sc);
    cudaGetSymbolAddress((void**)&vals0, s_vals0);
    cudaGetSymbolAddress((void**)&vals1, s_vals1);
    cudaGetSymbolAddress((void**)&idx0, s_idx0);
    cudaGetSymbolAddress((void**)&idx1, s_idx1);
    cudaGetSymbolAddress((void**)&inv,  s_inv);
    cudaGetSymbolAddress((void**)&biasGS, s_biasGS);

    cudaFuncSetAttribute(mm3t_kernel,
                         cudaFuncAttributeMaxDynamicSharedMemorySize, GSMEM);

    // down-path tf32x3 GEMM (exact selection arithmetic)
    auto gemm_tf = [&](int M, int N, int K,
                       const float* Ap, int lda, const float2* Bp,
                       const float* bias, float* Cp, int ldc,
                       const float* res, int ldres, int act) {
        dim3 grid(N / 64, (M + 63) / 64, 2);
        mm3t_kernel<<<grid, 128, GSMEM>>>(M, N, K / 2, Ap, lda, Bp, DD, part);
        int total = (M * N) / 4;
        finish_kernel<<<(total + 255) / 256, 256>>>(M, N, part, bias, Cp, ldc,
                                                    res, ldres, act);
    };
    // up-path bf16x3 GEMM (post-selection, fast path)
    auto gemm_bf = [&](int M, int N, int K,
                       const float* Ap, int lda, const unsigned* Bfp,
                       const float* bias, float* Cp, int ldc,
                       const float* res, int ldres, int act) {
        dim3 grid(N / 64, (M + 63) / 64, 2);
        mmbf_kernel<<<grid, 128, GS_BF>>>(M, N, K / 2, Ap, lda, Bfp, part);
        int total = (M * N) / 4;
        finish_kernel<<<(total + 255) / 256, 256>>>(M, N, part, bias, Cp, ldc,
                                                    res, ldres, act);
    };

    // ---- setup ----
    prep_tf32<<<(TF32_TOT + 255) / 256, 256>>>(W0, dW, Ws);
    prep_frag<<<(FRAG_SITES + 255) / 256, 256>>>(Wb, agWg, agWs, agWp, uW, We, Fr);
    mask_build<<<(N0 * N0) / 256, 256>>>(A, bm);
    bias_sum<<<3, 256>>>(agbg, agbs, biasGS, 2 * DD);

    // ---- encoder / down path (tf32x3) ----
    gemm_tf(N0, DD, DD, Xin, DD, Ws + OFF_W0, b0, X0, DD, nullptr, 0, 1);
    gemm_tf(N0, DD, DD, X0, DD, Ws + OFF_DW0, db, X1d, DD, nullptr, 0, 1);

    gemv_score<<<(N0 + 7) / 8, 256>>>(N0, X1d, pW, pwb, pb, phi, h1, e, eh);
    agg_l0<<<N0, 128>>>(bm, e, eh, sc);
    topk_rank<<<(N0 + 255) / 256, 256>>>(sc, N0, KK0, idx0, vals0);
    pool_gather<<<(KK0 * DD + 255) / 256, 256>>>(X1d, idx0, vals0, KK0, X1);

    gemm_tf(KK0, DD, DD, X1, DD, Ws + OFF_DW1, db + DD, X2d, DD, nullptr, 0, 1);

    gemv_score<<<(KK0 + 7) / 8, 256>>>(KK0, X2d, pW + DD, pwb + 1, pb + 1, phi + 2, h1, e, eh);
    agg_l1<<<KK0, 256>>>(bm, idx0, KK0, e, eh, sc);
    topk_rank<<<(KK0 + 255) / 256, 256>>>(sc, KK0, KK1, idx1, vals1);
    pool_gather<<<(KK1 * DD + 255) / 256, 256>>>(X2d, idx1, vals1, KK1, X2);

    // ---- bottleneck + up path (bf16x3) ----
    gemm_bf(KK1, DD, DD, X2, DD, Fr + FB_WB, bb, Xb, DD, nullptr, 0, 1);

    inv_init<<<(KK0 + 255) / 256, 256>>>(inv, KK0);
    inv_set<<<(KK1 + 255) / 256, 256>>>(inv, idx1, KK1);
    cat_fill<<<(KK0 * DD + 255) / 256, 256>>>(cat, inv, Xb, X2d, KK0);
    gemm_bf(KK0, DD, DD2, cat, DD2, Fr + FB_CATW0, biasGS, G, DD, nullptr, 0, 1);
    gemm_bf(KK0, DD, DD,  G,   DD,  Fr + FB_AGP0, agbp, cat + DD, DD2, nullptr, 0, 2);
    gemm_bf(KK0, DD, DD2, cat, DD2, Fr + FB_UW0, ub, Xu1, DD, X2d, DD, 1);

    inv_init<<<(N0 + 255) / 256, 256>>>(inv, N0);
    inv_set<<<(KK0 + 255) / 256, 256>>>(inv, idx0, KK0);
    cat_fill<<<(N0 * DD + 255) / 256, 256>>>(cat, inv, Xu1, X1d, N0);
    gemm_bf(N0, DD, DD2, cat, DD2, Fr + FB_CATW1, biasGS + DD, G, DD, nullptr, 0, 1);
    gemm_bf(N0, DD, DD,  G,   DD,  Fr + FB_AGP1, agbp + DD, cat + DD, DD2, nullptr, 0, 2);
    gemm_bf(N0, DD, DD2, cat, DD2, Fr + FB_UW1, ub + DD, Xu0, DD, X1d, DD, 1);

    // ---- head ----
    head_fill<<<(N0 * DD + 255) / 256, 256>>>(cat, Xu0, X0, N0);
    gemm_bf(N0, DD, DD2, cat, DD2, Fr + FB_WE, be, (float*)d_out, DD, nullptr, 0, 1);

    if (out_size >= 2 * N0 * DD) {
        cudaMemcpyAsync((float*)d_out + (size_t)N0 * DD, X0,
                        (size_t)N0 * DD * sizeof(float), cudaMemcpyDeviceToDevice, 0);
    }
}